// round 2
// baseline (speedup 1.0000x reference)
#include <cuda_runtime.h>
#include <cstdint>
#include <math.h>

#define NMAXA 8192
#define PMAXP 131072

// ---------------- device scratch (static: no runtime allocations) ----------------
__device__ float g_cgw[4096];                      // dense CG [aF][bF][MF], zero-padded
__device__ float g_emb[NMAXA * 32];                // center embeddings
__device__ float g_feats[(size_t)NMAXA * 1920];    // features (flattened per atom)
__device__ float g_feats2[(size_t)NMAXA * 1920];   // embedded features (ef)
__device__ float g_S[NMAXA * 240];                 // invariant MP per-(center,species) sh x rb
__device__ int   g_counts[NMAXA];
__device__ int   g_starts[NMAXA];
__device__ int   g_cursor[NMAXA];
__device__ int   g_sorted[PMAXP];

struct CGBuf { float v[3436]; };

__device__ __forceinline__ int foff(int l)  { return l==0?0:l==1?256:l==2?832:1472; }
__device__ __forceinline__ int klen(int l)  { return l==0?256:l==1?192:l==2?128:64; }
__device__ __forceinline__ int shoff(int l) { return l==0?0:l==1?1:l==2?4:9; }

// 34 valid (l1,l2,L) CG entries, in numpy generation order, with flat offsets
__constant__ int c_e_l1[34]={0,0,0,0, 1,1,1,1,1,1,1,1,1, 2,2,2,2,2,2,2,2,2,2,2, 3,3,3,3,3,3,3,3,3,3};
__constant__ int c_e_l2[34]={0,1,2,3, 0,1,1,1,2,2,2,3,3, 0,1,1,1,2,2,2,2,3,3,3, 0,1,1,2,2,2,3,3,3,3};
__constant__ int c_e_L [34]={0,1,2,3, 1,0,1,2,1,2,3,2,3, 2,1,2,3,0,1,2,3,1,2,3, 3,2,3,1,2,3,0,1,2,3};
__constant__ int c_e_off[34]={0,1,10,35, 84,93,102,129,174,219,294,399,504,
                              651,676,721,796,901,926,1001,1126,1301,1406,1581,
                              1826,1875,1980,2127,2232,2407,2652,2701,2848,3093};

// ---------------- CGW build (one block) ----------------
__global__ void k_initcg(CGBuf cg) {
    int t = threadIdx.x;
    for (int i = t; i < 4096; i += 256) g_cgw[i] = 0.f;
    __syncthreads();
    for (int e = 0; e < 34; e++) {
        int l1 = c_e_l1[e], l2 = c_e_l2[e], L = c_e_L[e];
        int d2 = 2*l2+1, dL = 2*L+1;
        int sz = (2*l1+1)*d2*dL, off = c_e_off[e];
        for (int i = t; i < sz; i += 256) {
            int M = i % dL; int r = i / dL; int b = r % d2; int a = r / d2;
            g_cgw[(shoff(l1)+a)*256 + (shoff(l2)+b)*16 + shoff(L)+M] = cg.v[off + i];
        }
    }
}

// ---------------- embeddings, sort ----------------
__global__ void k_emb(const float* __restrict__ tab, const int* __restrict__ spec, int N) {
    int i = blockIdx.x * blockDim.x + threadIdx.x;
    if (i < N * 32) g_emb[i] = tab[spec[i >> 5] * 32 + (i & 31)];
}

__global__ void k_zeroCS(int N) {
    int i = blockIdx.x * blockDim.x + threadIdx.x;
    if (i < N) g_counts[i] = 0;
    if (i < N * 240) g_S[i] = 0.f;
}

__global__ void k_hist(const int* __restrict__ centers, int P) {
    int p = blockIdx.x * blockDim.x + threadIdx.x;
    if (p < P) atomicAdd(&g_counts[centers[p]], 1);
}

__global__ void k_scan(int N) {
    __shared__ int sh[1024];
    __shared__ int sCarry;
    int t = threadIdx.x;
    if (t == 0) sCarry = 0;
    __syncthreads();
    for (int base = 0; base < N; base += 1024) {
        int i = base + t;
        int v = (i < N) ? g_counts[i] : 0;
        sh[t] = v; __syncthreads();
        for (int off = 1; off < 1024; off <<= 1) {
            int tv = (t >= off) ? sh[t - off] : 0;
            __syncthreads();
            sh[t] += tv;
            __syncthreads();
        }
        int ex = sCarry + sh[t] - v;
        if (i < N) { g_starts[i] = ex; g_cursor[i] = ex; }
        __syncthreads();
        if (t == 0) sCarry += sh[1023];
        __syncthreads();
    }
}

__global__ void k_scatter(const int* __restrict__ centers, int P) {
    int p = blockIdx.x * blockDim.x + threadIdx.x;
    if (p < P) { int pos = atomicAdd(&g_cursor[centers[p]], 1); g_sorted[pos] = p; }
}

// ---------------- invariant MP: per-(center,species) sh x rb outer product ----------------
__global__ void k_invA(const float* __restrict__ sh, const float* __restrict__ rb,
                       const int* __restrict__ centers, const int* __restrict__ neighbors,
                       const int* __restrict__ spec, int P) {
    int idx = blockIdx.x * blockDim.x + threadIdx.x;
    int p = idx >> 6, j = idx & 63;
    if (p >= P || j >= 60) return;
    int l, m, nr;
    if (j < 8)       { l = 0; m = 0;        nr = j; }
    else if (j < 26) { l = 1; int r = j-8;  m = r/6; nr = r%6; }
    else if (j < 46) { l = 2; int r = j-26; m = r/4; nr = r%4; }
    else             { l = 3; int r = j-46; m = r/2; nr = r%2; }
    int shf = shoff(l) + m;
    int rbf = (l==0?0:l==1?8:l==2?14:18) + nr;
    float val = sh[p*16 + shf] * 0.1f * rb[p*20 + rbf];   // 0.1 = NU_SCALING on sh
    int s = spec[neighbors[p]];
    atomicAdd(&g_S[(centers[p]*4 + s)*60 + j], val);
}

__global__ void k_invB(const float* __restrict__ tab, int N) {
    int idx = blockIdx.x * blockDim.x + threadIdx.x;
    if (idx >= N * 1920) return;
    int n = idx / 1920, f = idx % 1920;
    int l, m, k;
    if (f < 256)       { l = 0; m = 0;         k = f; }
    else if (f < 832)  { l = 1; int r = f-256; m = r/192; k = r%192; }
    else if (f < 1472) { l = 2; int r = f-832; m = r/128; k = r%128; }
    else               { l = 3; int r = f-1472;m = r/64;  k = r%64; }
    int nr = k >> 5, c = k & 31;
    int nrl = (l==0?8:l==1?6:l==2?4:2);
    int jb  = (l==0?0:l==1?8:l==2?26:46);
    int j = jb + m*nrl + nr;
    const float* Sp = &g_S[n*240 + j];
    float s = 0.f;
    #pragma unroll
    for (int sp = 0; sp < 4; sp++) s += Sp[sp*60] * tab[sp*32 + c];
    g_feats[(size_t)n*1920 + f] = 0.1f * s;               // MP_SCALING
}

// ---------------- tensor product (cg_iterate step): g += 0.1 * TP(g,g) ----------------
template<int NF>
__device__ __forceinline__ void tp_body(float* row, int k, const float* sC, const int* sOfs) {
    float A[NF];
    #pragma unroll
    for (int aF = 0; aF < NF; aF++) A[aF] = row[sOfs[aF] + k];
    float acc[NF];
    #pragma unroll
    for (int i = 0; i < NF; i++) acc[i] = 0.f;
    #pragma unroll 1
    for (int aF = 0; aF < NF; aF++) {
        float pa = row[sOfs[aF] + k];                     // reload (L1 hit) avoids dyn reg index
        const float* cgA = sC + aF*256;
        #pragma unroll
        for (int bF = 0; bF < NF; bF++) {
            float pab = pa * A[bF];
            #pragma unroll
            for (int M = 0; M < NF; M++) acc[M] += pab * cgA[bF*16 + M];
        }
    }
    #pragma unroll
    for (int M = 0; M < NF; M++) row[sOfs[M] + k] = A[M] + 0.1f * acc[M];  // NU_SCALING
}

__global__ void __launch_bounds__(256) k_tp(int N) {
    __shared__ float sC[4096];
    __shared__ int sOfs[16];
    int t = threadIdx.x;
    for (int i = t; i < 4096; i += 256) sC[i] = g_cgw[i];
    if (t < 16) {
        int l = (t==0)?0:(t<4)?1:(t<9)?2:3;
        sOfs[t] = foff(l) + (t - shoff(l)) * klen(l);
    }
    __syncthreads();
    float* row = g_feats + (size_t)blockIdx.x * 1920;
    int k = t;
    if (k < 64)       tp_body<16>(row, k, sC, sOfs);
    else if (k < 128) tp_body<9>(row, k, sC, sOfs);
    else if (k < 192) tp_body<4>(row, k, sC, sOfs);
    else              tp_body<1>(row, k, sC, sOfs);
}

// ---------------- ef = feats * center_emb (channelwise) ----------------
__global__ void k_ef(int N) {
    size_t idx = blockIdx.x * (size_t)blockDim.x + threadIdx.x;
    if (idx >= (size_t)N * 1920) return;
    int n = (int)(idx / 1920); int f = (int)(idx % 1920);
    g_feats2[idx] = g_feats[idx] * g_emb[n*32 + (f & 31)];
}

// ---------------- equivariant MP: one CTA per center ----------------
__global__ void __launch_bounds__(256) k_eqmp(const float* __restrict__ sh,
                                              const float* __restrict__ rb,
                                              const int* __restrict__ neighbors, int N) {
    __shared__ float sC[4096];
    __shared__ float sW[256];
    __shared__ float sE[16];
    int t = threadIdx.x, n = blockIdx.x;
    for (int i = t; i < 4096; i += 256) sC[i] = g_cgw[i];

    // per-thread output slot metadata: f = j*256 + t
    int kj[8], Mj[8], lmx[8];
    float acc[8];
    #pragma unroll
    for (int j = 0; j < 8; j++) {
        int f = j*256 + t;
        acc[j] = 0.f;
        if (f < 1920) {
            int L, M, k;
            if (f < 256)       { L = 0; M = 0;          k = f; }
            else if (f < 832)  { int r = f-256;  L = 1; M = r/192; k = r%192; }
            else if (f < 1472) { int r = f-832;  L = 2; M = r/128; k = r%128; }
            else               { int r = f-1472; L = 3; M = r/64;  k = r%64; }
            kj[j] = k; Mj[j] = shoff(L) + M;
            lmx[j] = (k < 64) ? 3 : (k < 128) ? 2 : (k < 192) ? 1 : 0;
        } else { kj[j] = 0; Mj[j] = 0; lmx[j] = -1; }
    }
    int start = g_starts[n], cnt = g_counts[n];
    __syncthreads();

    for (int e = 0; e < cnt; e++) {
        int p = g_sorted[start + e];
        int nbr = neighbors[p];
        if (t < 16) {                                        // edge[l][a] = sh*0.1 * sum(rb_l)
            int l = (t==0)?0:(t<4)?1:(t<9)?2:3;
            int nrl = (l==0?8:l==1?6:l==2?4:2);
            int rbo = (l==0?0:l==1?8:l==2?14:18);
            float s = 0.f;
            for (int r = 0; r < nrl; r++) s += rb[p*20 + rbo + r];
            sE[t] = sh[p*16 + t] * 0.1f * s;
        }
        __syncthreads();
        {                                                    // W[bF,MF] = sum_aF edge * CG
            float w = 0.f;
            #pragma unroll
            for (int aF = 0; aF < 16; aF++) w += sE[aF] * sC[aF*256 + t];
            sW[t] = w;
        }
        __syncthreads();
        const float* efr = g_feats2 + (size_t)nbr * 1920;
        #pragma unroll
        for (int j = 0; j < 8; j++) {
            if (lmx[j] < 0) continue;
            int k = kj[j], M = Mj[j];
            float s = sW[M] * efr[k];                        // l2 = 0
            if (lmx[j] >= 1) {                               // l2 = 1
                s += sW[16+M]*efr[256+k];
                s += sW[32+M]*efr[448+k];
                s += sW[48+M]*efr[640+k];
            }
            if (lmx[j] >= 2) {                               // l2 = 2
                s += sW[64+M] *efr[832+k];
                s += sW[80+M] *efr[960+k];
                s += sW[96+M] *efr[1088+k];
                s += sW[112+M]*efr[1216+k];
                s += sW[128+M]*efr[1344+k];
            }
            if (lmx[j] >= 3) {                               // l2 = 3
                s += sW[144+M]*efr[1472+k];
                s += sW[160+M]*efr[1536+k];
                s += sW[176+M]*efr[1600+k];
                s += sW[192+M]*efr[1664+k];
                s += sW[208+M]*efr[1728+k];
                s += sW[224+M]*efr[1792+k];
                s += sW[240+M]*efr[1856+k];
            }
            acc[j] += s;
        }
        __syncthreads();
    }
    #pragma unroll
    for (int j = 0; j < 8; j++) {
        int f = j*256 + t;
        if (f < 1920) g_feats[(size_t)n*1920 + f] = 0.1f * acc[j];   // MP_SCALING
    }
}

// ---------------- energy readout ----------------
__global__ void __launch_bounds__(256) k_energy(const float* __restrict__ wE,
                                                const float* __restrict__ bE,
                                                float* __restrict__ out, int N) {
    int n = blockIdx.x, t = threadIdx.x;
    float v = g_feats[(size_t)n*1920 + t] * g_emb[n*32 + (t & 31)] * wE[t];
    #pragma unroll
    for (int o = 16; o > 0; o >>= 1) v += __shfl_xor_sync(0xffffffffu, v, o);
    __shared__ float sred[8];
    if ((t & 31) == 0) sred[t >> 5] = v;
    __syncthreads();
    if (t == 0) {
        float s = 0.f;
        #pragma unroll
        for (int w = 0; w < 8; w++) s += sred[w];
        out[n] = s + bE[0];
    }
}

// ---------------- host: numpy RandomState(0).randn reimplementation ----------------
static void gen_cg(float* out) {
    static uint32_t mt[624];
    int mti;
    mt[0] = 0;
    for (int i = 1; i < 624; i++)
        mt[i] = 1812433253u * (mt[i-1] ^ (mt[i-1] >> 30)) + (uint32_t)i;
    mti = 624;
    auto genrand = [&]() -> uint32_t {
        if (mti >= 624) {
            for (int i = 0; i < 624; i++) {
                uint32_t y = (mt[i] & 0x80000000u) | (mt[(i+1) % 624] & 0x7fffffffu);
                mt[i] = mt[(i+397) % 624] ^ (y >> 1) ^ ((y & 1u) ? 2567483615u : 0u);
            }
            mti = 0;
        }
        uint32_t y = mt[mti++];
        y ^= y >> 11; y ^= (y << 7) & 2636928640u; y ^= (y << 15) & 4022730752u; y ^= y >> 18;
        return y;
    };
    auto rdouble = [&]() -> double {
        uint32_t a = genrand() >> 5, b = genrand() >> 6;
        return (a * 67108864.0 + b) / 9007199254740992.0;
    };
    bool has_g = false; double gcache = 0.0;
    auto gauss = [&]() -> double {
        if (has_g) { has_g = false; return gcache; }
        double x1, x2, r2;
        do {
            x1 = 2.0 * rdouble() - 1.0;
            x2 = 2.0 * rdouble() - 1.0;
            r2 = x1*x1 + x2*x2;
        } while (r2 >= 1.0 || r2 == 0.0);
        double f = sqrt(-2.0 * log(r2) / r2);
        gcache = f * x1; has_g = true;
        return f * x2;
    };
    for (int i = 0; i < 3436; i++) out[i] = (float)(gauss() * 0.2);
}

static CGBuf h_cg;

extern "C" void kernel_launch(void* const* d_in, const int* in_sizes, int n_in,
                              void* d_out, int out_size) {
    const float* sh      = (const float*)d_in[0];
    const float* rb      = (const float*)d_in[1];
    const float* tab     = (const float*)d_in[2];
    const float* wE      = (const float*)d_in[3];
    const float* bE      = (const float*)d_in[4];
    const int*   spec    = (const int*)d_in[5];
    const int*   centers = (const int*)d_in[6];
    const int*   nbrs    = (const int*)d_in[7];
    int N = in_sizes[5];
    int P = in_sizes[6];
    float* out = (float*)d_out;

    gen_cg(h_cg.v);   // deterministic; recomputed every call

    k_initcg<<<1, 256>>>(h_cg);
    k_emb<<<(N*32 + 255)/256, 256>>>(tab, spec, N);
    k_zeroCS<<<(N*240 + 255)/256, 256>>>(N);
    k_hist<<<(P + 255)/256, 256>>>(centers, P);
    k_scan<<<1, 1024>>>(N);
    k_scatter<<<(P + 255)/256, 256>>>(centers, P);
    k_invA<<<(P*64 + 255)/256, 256>>>(sh, rb, centers, nbrs, spec, P);
    k_invB<<<(N*1920 + 255)/256, 256>>>(tab, N);
    k_tp<<<N, 256>>>(N);
    k_ef<<<(N*1920 + 255)/256, 256>>>(N);
    k_eqmp<<<N, 256>>>(sh, rb, nbrs, N);
    k_tp<<<N, 256>>>(N);
    k_energy<<<N, 256>>>(wE, bE, out, N);
}

// round 3
// speedup vs baseline: 2.1197x; 2.1197x over previous
#include <cuda_runtime.h>
#include <cstdint>
#include <math.h>

#define NMAXA 8192
#define PMAXP 131072

// ---------------- device scratch ----------------
__device__ float g_cgw[4096];                      // dense CG [aF][bF][MF]
__device__ float g_sym0[136 * 16];                 // symmetrized CG, NF16 class
__device__ float g_sym1[45 * 16];                  // NF9 class (M stride 16)
__device__ float g_sym2[10 * 4];                   // NF4 class
__device__ float g_c000[1];
__device__ float g_emb[NMAXA * 32];
__device__ float g_feats[(size_t)NMAXA * 1920];
__device__ float g_feats2[(size_t)NMAXA * 1920];
__device__ float g_S[NMAXA * 240];
__device__ int   g_counts[NMAXA];
__device__ int   g_starts[NMAXA];
__device__ int   g_cursor[NMAXA];
__device__ int   g_sorted[PMAXP];

struct CGBuf { float v[3436]; };

__device__ __forceinline__ int shoff(int l) { return l==0?0:l==1?1:l==2?4:9; }

__constant__ int c_e_l1[34]={0,0,0,0, 1,1,1,1,1,1,1,1,1, 2,2,2,2,2,2,2,2,2,2,2, 3,3,3,3,3,3,3,3,3,3};
__constant__ int c_e_l2[34]={0,1,2,3, 0,1,1,1,2,2,2,3,3, 0,1,1,1,2,2,2,2,3,3,3, 0,1,1,2,2,2,3,3,3,3};
__constant__ int c_e_L [34]={0,1,2,3, 1,0,1,2,1,2,3,2,3, 2,1,2,3,0,1,2,3,1,2,3, 3,2,3,1,2,3,0,1,2,3};
__constant__ int c_e_off[34]={0,1,10,35, 84,93,102,129,174,219,294,399,504,
                              651,676,721,796,901,926,1001,1126,1301,1406,1581,
                              1826,1875,1980,2127,2232,2407,2652,2701,2848,3093};

#define FMA2(ACC,PD,CV) asm("fma.rn.f32x2 %0, %1, %2, %0;" : "+l"(ACC) : "l"(PD), "l"(CV))
#define PACK2(PD,P)     asm("mov.b64 %0, {%1, %1};" : "=l"(PD) : "f"(P))
#define UNPK2(LO,HI,PD) asm("mov.b64 {%0, %1}, %2;" : "=f"(LO), "=f"(HI) : "l"(PD))

// ---------------- CG build ----------------
__global__ void k_initcg(CGBuf cg) {
    int t = threadIdx.x;
    for (int i = t; i < 4096; i += 256) g_cgw[i] = 0.f;
    __syncthreads();
    for (int e = 0; e < 34; e++) {
        int l1 = c_e_l1[e], l2 = c_e_l2[e], L = c_e_L[e];
        int d2 = 2*l2+1, dL = 2*L+1;
        int sz = (2*l1+1)*d2*dL, off = c_e_off[e];
        for (int i = t; i < sz; i += 256) {
            int M = i % dL; int r = i / dL; int b = r % d2; int a = r / d2;
            g_cgw[(shoff(l1)+a)*256 + (shoff(l2)+b)*16 + shoff(L)+M] = cg.v[off + i];
        }
        __syncthreads();
    }
    // symmetrized variants
    for (int i = t; i < 136*16; i += 256) {
        int pi = i >> 4, M = i & 15;
        int a = 0, base = 0;
        while (base + (16 - a) <= pi) { base += 16 - a; a++; }
        int b = a + (pi - base);
        float v = g_cgw[a*256 + b*16 + M];
        if (a != b) v += g_cgw[b*256 + a*16 + M];
        g_sym0[i] = v;
    }
    for (int i = t; i < 45*16; i += 256) {
        int pi = i >> 4, M = i & 15;
        int a = 0, base = 0;
        while (base + (9 - a) <= pi) { base += 9 - a; a++; }
        int b = a + (pi - base);
        float v = 0.f;
        if (M < 9) {
            v = g_cgw[a*256 + b*16 + M];
            if (a != b) v += g_cgw[b*256 + a*16 + M];
        }
        g_sym1[i] = v;
    }
    for (int i = t; i < 40; i += 256) {
        int pi = i >> 2, M = i & 3;
        int a = 0, base = 0;
        while (base + (4 - a) <= pi) { base += 4 - a; a++; }
        int b = a + (pi - base);
        float v = g_cgw[a*256 + b*16 + M];
        if (a != b) v += g_cgw[b*256 + a*16 + M];
        g_sym2[i] = v;
    }
    if (t == 0) g_c000[0] = g_cgw[0];
}

// ---------------- embeddings, counting sort ----------------
__global__ void k_emb(const float* __restrict__ tab, const int* __restrict__ spec, int N) {
    int i = blockIdx.x * blockDim.x + threadIdx.x;
    if (i < N * 32) g_emb[i] = tab[spec[i >> 5] * 32 + (i & 31)];
}

__global__ void k_zeroCS(int N) {
    int i = blockIdx.x * blockDim.x + threadIdx.x;
    if (i < N) g_counts[i] = 0;
    if (i < N * 240) g_S[i] = 0.f;
}

__global__ void k_hist(const int* __restrict__ centers, int P) {
    int p = blockIdx.x * blockDim.x + threadIdx.x;
    if (p < P) atomicAdd(&g_counts[centers[p]], 1);
}

__global__ void k_scan(int N) {
    __shared__ int sh[1024];
    __shared__ int sCarry;
    int t = threadIdx.x;
    if (t == 0) sCarry = 0;
    __syncthreads();
    for (int base = 0; base < N; base += 1024) {
        int i = base + t;
        int v = (i < N) ? g_counts[i] : 0;
        sh[t] = v; __syncthreads();
        for (int off = 1; off < 1024; off <<= 1) {
            int tv = (t >= off) ? sh[t - off] : 0;
            __syncthreads();
            sh[t] += tv;
            __syncthreads();
        }
        int ex = sCarry + sh[t] - v;
        if (i < N) { g_starts[i] = ex; g_cursor[i] = ex; }
        __syncthreads();
        if (t == 0) sCarry += sh[1023];
        __syncthreads();
    }
}

__global__ void k_scatter(const int* __restrict__ centers, int P) {
    int p = blockIdx.x * blockDim.x + threadIdx.x;
    if (p < P) { int pos = atomicAdd(&g_cursor[centers[p]], 1); g_sorted[pos] = p; }
}

// ---------------- invariant MP ----------------
__global__ void k_invA(const float* __restrict__ sh, const float* __restrict__ rb,
                       const int* __restrict__ centers, const int* __restrict__ neighbors,
                       const int* __restrict__ spec, int P) {
    int idx = blockIdx.x * blockDim.x + threadIdx.x;
    int p = idx >> 6, j = idx & 63;
    if (p >= P || j >= 60) return;
    int l, m, nr;
    if (j < 8)       { l = 0; m = 0;        nr = j; }
    else if (j < 26) { l = 1; int r = j-8;  m = r/6; nr = r%6; }
    else if (j < 46) { l = 2; int r = j-26; m = r/4; nr = r%4; }
    else             { l = 3; int r = j-46; m = r/2; nr = r%2; }
    int shf = shoff(l) + m;
    int rbf = (l==0?0:l==1?8:l==2?14:18) + nr;
    float val = sh[p*16 + shf] * 0.1f * rb[p*20 + rbf];
    int s = spec[neighbors[p]];
    atomicAdd(&g_S[(centers[p]*4 + s)*60 + j], val);
}

__global__ void k_invB(const float* __restrict__ tab, int N) {
    int idx = blockIdx.x * blockDim.x + threadIdx.x;
    if (idx >= N * 1920) return;
    int n = idx / 1920, f = idx % 1920;
    int l, m, k;
    if (f < 256)       { l = 0; m = 0;         k = f; }
    else if (f < 832)  { l = 1; int r = f-256; m = r/192; k = r%192; }
    else if (f < 1472) { l = 2; int r = f-832; m = r/128; k = r%128; }
    else               { l = 3; int r = f-1472;m = r/64;  k = r%64; }
    int nr = k >> 5, c = k & 31;
    int nrl = (l==0?8:l==1?6:l==2?4:2);
    int jb  = (l==0?0:l==1?8:l==2?26:46);
    int j = jb + m*nrl + nr;
    const float* Sp = &g_S[n*240 + j];
    float s = 0.f;
    #pragma unroll
    for (int sp = 0; sp < 4; sp++) s += Sp[sp*60] * tab[sp*32 + c];
    g_feats[(size_t)n*1920 + f] = 0.1f * s;
}

// ---------------- tensor product, per k-class (balanced, symmetric, f32x2) ----------------
// flat-(l,m) row offsets into a feature row
// offs = {0,256,448,640, 832,960,1088,1216,1344, 1472,1536,1600,1664,1728,1792,1856}

__global__ void __launch_bounds__(256) k_tp0(int N) {   // k in [0,64): NF=16
    __shared__ float sC[136 * 16];
    int t = threadIdx.x;
    for (int i = t; i < 2176; i += 256) sC[i] = g_sym0[i];
    __syncthreads();
    int atom = blockIdx.x * 4 + (t >> 6);
    if (atom >= N) return;
    float* row = g_feats + (size_t)atom * 1920 + (t & 63);
    float A[16];
    A[0]=row[0];    A[1]=row[256];  A[2]=row[448];  A[3]=row[640];
    A[4]=row[832];  A[5]=row[960];  A[6]=row[1088]; A[7]=row[1216]; A[8]=row[1344];
    A[9]=row[1472]; A[10]=row[1536];A[11]=row[1600];A[12]=row[1664];
    A[13]=row[1728];A[14]=row[1792];A[15]=row[1856];
    unsigned long long acc[8];
    #pragma unroll
    for (int i = 0; i < 8; i++) acc[i] = 0ull;
    #pragma unroll
    for (int a = 0; a < 16; a++) {
        #pragma unroll
        for (int b = a; b < 16; b++) {
            const int pi = a*16 - a*(a-1)/2 + (b - a);
            float P = A[a] * A[b];
            unsigned long long Pd; PACK2(Pd, P);
            const ulonglong2* c2 = (const ulonglong2*)(sC + pi*16);
            ulonglong2 cv0 = c2[0];
            ulonglong2 cv1 = c2[1];
            FMA2(acc[0], Pd, cv0.x); FMA2(acc[1], Pd, cv0.y);
            FMA2(acc[2], Pd, cv1.x); FMA2(acc[3], Pd, cv1.y);
            ulonglong2 cv2 = c2[2];
            ulonglong2 cv3 = c2[3];
            FMA2(acc[4], Pd, cv2.x); FMA2(acc[5], Pd, cv2.y);
            FMA2(acc[6], Pd, cv3.x); FMA2(acc[7], Pd, cv3.y);
        }
    }
    float v[16];
    #pragma unroll
    for (int i = 0; i < 8; i++) UNPK2(v[2*i], v[2*i+1], acc[i]);
    row[0]   =A[0] +0.1f*v[0];  row[256] =A[1] +0.1f*v[1];  row[448] =A[2] +0.1f*v[2];
    row[640] =A[3] +0.1f*v[3];  row[832] =A[4] +0.1f*v[4];  row[960] =A[5] +0.1f*v[5];
    row[1088]=A[6] +0.1f*v[6];  row[1216]=A[7] +0.1f*v[7];  row[1344]=A[8] +0.1f*v[8];
    row[1472]=A[9] +0.1f*v[9];  row[1536]=A[10]+0.1f*v[10]; row[1600]=A[11]+0.1f*v[11];
    row[1664]=A[12]+0.1f*v[12]; row[1728]=A[13]+0.1f*v[13]; row[1792]=A[14]+0.1f*v[14];
    row[1856]=A[15]+0.1f*v[15];
}

__global__ void __launch_bounds__(256) k_tp1(int N) {   // k in [64,128): NF=9
    __shared__ float sC[45 * 16];
    int t = threadIdx.x;
    for (int i = t; i < 720; i += 256) sC[i] = g_sym1[i];
    __syncthreads();
    int atom = blockIdx.x * 4 + (t >> 6);
    if (atom >= N) return;
    float* row = g_feats + (size_t)atom * 1920 + 64 + (t & 63);
    float A[9];
    A[0]=row[0];   A[1]=row[256]; A[2]=row[448]; A[3]=row[640];
    A[4]=row[832]; A[5]=row[960]; A[6]=row[1088];A[7]=row[1216];A[8]=row[1344];
    unsigned long long acc[4];
    #pragma unroll
    for (int i = 0; i < 4; i++) acc[i] = 0ull;
    float acc8 = 0.f;
    #pragma unroll
    for (int a = 0; a < 9; a++) {
        #pragma unroll
        for (int b = a; b < 9; b++) {
            const int pi = a*9 - a*(a-1)/2 + (b - a);
            float P = A[a] * A[b];
            unsigned long long Pd; PACK2(Pd, P);
            const ulonglong2* c2 = (const ulonglong2*)(sC + pi*16);
            ulonglong2 cv0 = c2[0];
            ulonglong2 cv1 = c2[1];
            FMA2(acc[0], Pd, cv0.x); FMA2(acc[1], Pd, cv0.y);
            FMA2(acc[2], Pd, cv1.x); FMA2(acc[3], Pd, cv1.y);
            acc8 += P * sC[pi*16 + 8];
        }
    }
    float v[8];
    #pragma unroll
    for (int i = 0; i < 4; i++) UNPK2(v[2*i], v[2*i+1], acc[i]);
    row[0]   =A[0]+0.1f*v[0]; row[256] =A[1]+0.1f*v[1]; row[448] =A[2]+0.1f*v[2];
    row[640] =A[3]+0.1f*v[3]; row[832] =A[4]+0.1f*v[4]; row[960] =A[5]+0.1f*v[5];
    row[1088]=A[6]+0.1f*v[6]; row[1216]=A[7]+0.1f*v[7]; row[1344]=A[8]+0.1f*acc8;
}

__global__ void k_tp23(int N) {   // k in [128,192): NF=4 ; k in [192,256): NF=1
    int t = threadIdx.x;
    int atom = blockIdx.x * 2 + (t >> 7);
    if (atom >= N) return;
    int tt = t & 127;
    if (tt < 64) {
        float* row = g_feats + (size_t)atom * 1920 + 128 + tt;
        float A[4];
        A[0]=row[0]; A[1]=row[256]; A[2]=row[448]; A[3]=row[640];
        float acc[4] = {0.f, 0.f, 0.f, 0.f};
        #pragma unroll
        for (int a = 0; a < 4; a++) {
            #pragma unroll
            for (int b = a; b < 4; b++) {
                const int pi = a*4 - a*(a-1)/2 + (b - a);
                float P = A[a] * A[b];
                #pragma unroll
                for (int M = 0; M < 4; M++) acc[M] += P * g_sym2[pi*4 + M];
            }
        }
        row[0]  =A[0]+0.1f*acc[0]; row[256]=A[1]+0.1f*acc[1];
        row[448]=A[2]+0.1f*acc[2]; row[640]=A[3]+0.1f*acc[3];
    } else {
        float* row = g_feats + (size_t)atom * 1920 + 192 + (tt & 63);
        float A = row[0];
        row[0] = A + 0.1f * A * A * g_c000[0];
    }
}

// ---------------- ef = feats * center_emb ----------------
__global__ void k_ef(int N) {
    size_t idx = blockIdx.x * (size_t)blockDim.x + threadIdx.x;
    if (idx >= (size_t)N * 1920) return;
    int n = (int)(idx / 1920); int f = (int)(idx % 1920);
    g_feats2[idx] = g_feats[idx] * g_emb[n*32 + (f & 31)];
}

// ---------------- equivariant MP: CTA per center, shared-staged, 4-pair chunks ----------------
#define PB 4
__global__ void __launch_bounds__(256) k_eqmp(const float* __restrict__ sh,
                                              const float* __restrict__ rb,
                                              const int* __restrict__ neighbors, int N) {
    __shared__ float sEF[PB][1920];
    __shared__ float sW4[PB][256];
    __shared__ float sE4[PB][16];
    int t = threadIdx.x, n = blockIdx.x;

    int kj[8], Mj[8], lmx[8];
    float acc[8];
    #pragma unroll
    for (int j = 0; j < 8; j++) {
        int f = j*256 + t;
        acc[j] = 0.f;
        if (f < 1920) {
            int L, M, k;
            if (f < 256)       { L = 0; M = 0;          k = f; }
            else if (f < 832)  { int r = f-256;  L = 1; M = r/192; k = r%192; }
            else if (f < 1472) { int r = f-832;  L = 2; M = r/128; k = r%128; }
            else               { int r = f-1472; L = 3; M = r/64;  k = r%64; }
            kj[j] = k; Mj[j] = shoff(L) + M;
            lmx[j] = (k < 64) ? 3 : (k < 128) ? 2 : (k < 192) ? 1 : 0;
        } else { kj[j] = 0; Mj[j] = 0; lmx[j] = -1; }
    }
    float cA[16];
    #pragma unroll
    for (int a = 0; a < 16; a++) cA[a] = g_cgw[a*256 + t];

    int start = g_starts[n], cnt = g_counts[n];

    for (int e0 = 0; e0 < cnt; e0 += PB) {
        int nv = min(PB, cnt - e0);
        __syncthreads();
        // stage nv neighbor rows (coalesced float4)
        for (int pb = 0; pb < nv; pb++) {
            int p = g_sorted[start + e0 + pb];
            int nbr = neighbors[p];
            const float4* efr = (const float4*)(g_feats2 + (size_t)nbr * 1920);
            float4* dst = (float4*)sEF[pb];
            for (int i = t; i < 480; i += 256) dst[i] = efr[i];
        }
        // edge vectors
        if (t < PB*16) {
            int pb = t >> 4;
            if (pb < nv) {
                int a = t & 15;
                int p = g_sorted[start + e0 + pb];
                int l   = (a==0)?0:(a<4)?1:(a<9)?2:3;
                int nrl = (l==0?8:l==1?6:l==2?4:2);
                int rbo = (l==0?0:l==1?8:l==2?14:18);
                float s = 0.f;
                for (int r = 0; r < nrl; r++) s += rb[p*20 + rbo + r];
                sE4[pb][a] = sh[p*16 + a] * 0.1f * s;
            }
        }
        __syncthreads();
        // W[pb][bF*16+MF]
        #pragma unroll
        for (int pb = 0; pb < PB; pb++) {
            if (pb < nv) {
                float w = 0.f;
                #pragma unroll
                for (int a = 0; a < 16; a++) w += sE4[pb][a] * cA[a];
                sW4[pb][t] = w;
            }
        }
        __syncthreads();
        // contraction
        #pragma unroll
        for (int pb = 0; pb < PB; pb++) {
            if (pb < nv) {
                const float* EF = sEF[pb];
                const float* W  = sW4[pb];
                #pragma unroll
                for (int j = 0; j < 8; j++) {
                    if (lmx[j] < 0) continue;
                    int k = kj[j], M = Mj[j];
                    float s = W[M] * EF[k];
                    if (lmx[j] >= 1) {
                        s += W[16+M]*EF[256+k];
                        s += W[32+M]*EF[448+k];
                        s += W[48+M]*EF[640+k];
                    }
                    if (lmx[j] >= 2) {
                        s += W[64+M] *EF[832+k];
                        s += W[80+M] *EF[960+k];
                        s += W[96+M] *EF[1088+k];
                        s += W[112+M]*EF[1216+k];
                        s += W[128+M]*EF[1344+k];
                    }
                    if (lmx[j] >= 3) {
                        s += W[144+M]*EF[1472+k];
                        s += W[160+M]*EF[1536+k];
                        s += W[176+M]*EF[1600+k];
                        s += W[192+M]*EF[1664+k];
                        s += W[208+M]*EF[1728+k];
                        s += W[224+M]*EF[1792+k];
                        s += W[240+M]*EF[1856+k];
                    }
                    acc[j] += s;
                }
            }
        }
    }
    #pragma unroll
    for (int j = 0; j < 8; j++) {
        int f = j*256 + t;
        if (f < 1920) g_feats[(size_t)n*1920 + f] = 0.1f * acc[j];
    }
}

// ---------------- energy readout ----------------
__global__ void __launch_bounds__(256) k_energy(const float* __restrict__ wE,
                                                const float* __restrict__ bE,
                                                float* __restrict__ out, int N) {
    int n = blockIdx.x, t = threadIdx.x;
    float v = g_feats[(size_t)n*1920 + t] * g_emb[n*32 + (t & 31)] * wE[t];
    #pragma unroll
    for (int o = 16; o > 0; o >>= 1) v += __shfl_xor_sync(0xffffffffu, v, o);
    __shared__ float sred[8];
    if ((t & 31) == 0) sred[t >> 5] = v;
    __syncthreads();
    if (t == 0) {
        float s = 0.f;
        #pragma unroll
        for (int w = 0; w < 8; w++) s += sred[w];
        out[n] = s + bE[0];
    }
}

// ---------------- host: numpy RandomState(0).randn ----------------
static void gen_cg(float* out) {
    static uint32_t mt[624];
    int mti;
    mt[0] = 0;
    for (int i = 1; i < 624; i++)
        mt[i] = 1812433253u * (mt[i-1] ^ (mt[i-1] >> 30)) + (uint32_t)i;
    mti = 624;
    auto genrand = [&]() -> uint32_t {
        if (mti >= 624) {
            for (int i = 0; i < 624; i++) {
                uint32_t y = (mt[i] & 0x80000000u) | (mt[(i+1) % 624] & 0x7fffffffu);
                mt[i] = mt[(i+397) % 624] ^ (y >> 1) ^ ((y & 1u) ? 2567483615u : 0u);
            }
            mti = 0;
        }
        uint32_t y = mt[mti++];
        y ^= y >> 11; y ^= (y << 7) & 2636928640u; y ^= (y << 15) & 4022730752u; y ^= y >> 18;
        return y;
    };
    auto rdouble = [&]() -> double {
        uint32_t a = genrand() >> 5, b = genrand() >> 6;
        return (a * 67108864.0 + b) / 9007199254740992.0;
    };
    bool has_g = false; double gcache = 0.0;
    auto gauss = [&]() -> double {
        if (has_g) { has_g = false; return gcache; }
        double x1, x2, r2;
        do {
            x1 = 2.0 * rdouble() - 1.0;
            x2 = 2.0 * rdouble() - 1.0;
            r2 = x1*x1 + x2*x2;
        } while (r2 >= 1.0 || r2 == 0.0);
        double f = sqrt(-2.0 * log(r2) / r2);
        gcache = f * x1; has_g = true;
        return f * x2;
    };
    for (int i = 0; i < 3436; i++) out[i] = (float)(gauss() * 0.2);
}

static CGBuf h_cg;

extern "C" void kernel_launch(void* const* d_in, const int* in_sizes, int n_in,
                              void* d_out, int out_size) {
    const float* sh      = (const float*)d_in[0];
    const float* rb      = (const float*)d_in[1];
    const float* tab     = (const float*)d_in[2];
    const float* wE      = (const float*)d_in[3];
    const float* bE      = (const float*)d_in[4];
    const int*   spec    = (const int*)d_in[5];
    const int*   centers = (const int*)d_in[6];
    const int*   nbrs    = (const int*)d_in[7];
    int N = in_sizes[5];
    int P = in_sizes[6];
    float* out = (float*)d_out;

    gen_cg(h_cg.v);

    k_initcg<<<1, 256>>>(h_cg);
    k_emb<<<(N*32 + 255)/256, 256>>>(tab, spec, N);
    k_zeroCS<<<(N*240 + 255)/256, 256>>>(N);
    k_hist<<<(P + 255)/256, 256>>>(centers, P);
    k_scan<<<1, 1024>>>(N);
    k_scatter<<<(P + 255)/256, 256>>>(centers, P);
    k_invA<<<(P*64 + 255)/256, 256>>>(sh, rb, centers, nbrs, spec, P);
    k_invB<<<(N*1920 + 255)/256, 256>>>(tab, N);
    k_tp0<<<(N + 3)/4, 256>>>(N);
    k_tp1<<<(N + 3)/4, 256>>>(N);
    k_tp23<<<(N + 1)/2, 256>>>(N);
    k_ef<<<(N*1920 + 255)/256, 256>>>(N);
    k_eqmp<<<N, 256>>>(sh, rb, nbrs, N);
    k_tp0<<<(N + 3)/4, 256>>>(N);
    k_tp1<<<(N + 3)/4, 256>>>(N);
    k_tp23<<<(N + 1)/2, 256>>>(N);
    k_energy<<<N, 256>>>(wE, bE, out, N);
}

// round 4
// speedup vs baseline: 2.7944x; 1.3183x over previous
#include <cuda_runtime.h>
#include <cstdint>
#include <math.h>

#define NMAXA 8192
#define PMAXP 131072

typedef unsigned long long ull;

// ---------------- device scratch ----------------
__device__ float g_cgw[4096];                      // dense CG [aF][bF][MF]
__device__ float g_sym0[136 * 16];
__device__ float g_sym1[45 * 16];
__device__ float g_sym2[10 * 4];
__device__ float g_c000[1];
__device__ float g_emb[NMAXA * 32];
__device__ float g_feats[(size_t)NMAXA * 1920];
__device__ float g_feats2[(size_t)NMAXA * 1920];
__device__ float g_S[NMAXA * 240];
__device__ float g_W[(size_t)PMAXP * 256];         // per-pair W (sorted order)
__device__ int   g_snbr[PMAXP];                    // neighbor idx (sorted order)
__device__ int   g_counts[NMAXA];
__device__ int   g_starts[NMAXA];
__device__ int   g_cursor[NMAXA];
__device__ int   g_sorted[PMAXP];

struct CGBuf { float v[3436]; };

__device__ __forceinline__ int shoff(int l) { return l==0?0:l==1?1:l==2?4:9; }

// flat-(l,m) block offsets inside a 1920-feature row
__device__ constexpr int OFFS[16] = {0,256,448,640,832,960,1088,1216,1344,
                                     1472,1536,1600,1664,1728,1792,1856};

__constant__ int c_e_l1[34]={0,0,0,0, 1,1,1,1,1,1,1,1,1, 2,2,2,2,2,2,2,2,2,2,2, 3,3,3,3,3,3,3,3,3,3};
__constant__ int c_e_l2[34]={0,1,2,3, 0,1,1,1,2,2,2,3,3, 0,1,1,1,2,2,2,2,3,3,3, 0,1,1,2,2,2,3,3,3,3};
__constant__ int c_e_L [34]={0,1,2,3, 1,0,1,2,1,2,3,2,3, 2,1,2,3,0,1,2,3,1,2,3, 3,2,3,1,2,3,0,1,2,3};
__constant__ int c_e_off[34]={0,1,10,35, 84,93,102,129,174,219,294,399,504,
                              651,676,721,796,901,926,1001,1126,1301,1406,1581,
                              1826,1875,1980,2127,2232,2407,2652,2701,2848,3093};

#define FMA2(ACC,PD,CV) asm("fma.rn.f32x2 %0, %1, %2, %0;" : "+l"(ACC) : "l"(PD), "l"(CV))
#define PACK2(PD,P)     asm("mov.b64 %0, {%1, %1};" : "=l"(PD) : "f"(P))
#define UNPK2(LO,HI,PD) asm("mov.b64 {%0, %1}, %2;" : "=f"(LO), "=f"(HI) : "l"(PD))

// ---------------- CG build ----------------
__global__ void k_initcg(CGBuf cg) {
    int t = threadIdx.x;
    for (int i = t; i < 4096; i += 256) g_cgw[i] = 0.f;
    __syncthreads();
    for (int e = 0; e < 34; e++) {
        int l1 = c_e_l1[e], l2 = c_e_l2[e], L = c_e_L[e];
        int d2 = 2*l2+1, dL = 2*L+1;
        int sz = (2*l1+1)*d2*dL, off = c_e_off[e];
        for (int i = t; i < sz; i += 256) {
            int M = i % dL; int r = i / dL; int b = r % d2; int a = r / d2;
            g_cgw[(shoff(l1)+a)*256 + (shoff(l2)+b)*16 + shoff(L)+M] = cg.v[off + i];
        }
        __syncthreads();
    }
    for (int i = t; i < 136*16; i += 256) {
        int pi = i >> 4, M = i & 15;
        int a = 0, base = 0;
        while (base + (16 - a) <= pi) { base += 16 - a; a++; }
        int b = a + (pi - base);
        float v = g_cgw[a*256 + b*16 + M];
        if (a != b) v += g_cgw[b*256 + a*16 + M];
        g_sym0[i] = v;
    }
    for (int i = t; i < 45*16; i += 256) {
        int pi = i >> 4, M = i & 15;
        int a = 0, base = 0;
        while (base + (9 - a) <= pi) { base += 9 - a; a++; }
        int b = a + (pi - base);
        float v = 0.f;
        if (M < 9) {
            v = g_cgw[a*256 + b*16 + M];
            if (a != b) v += g_cgw[b*256 + a*16 + M];
        }
        g_sym1[i] = v;
    }
    for (int i = t; i < 40; i += 256) {
        int pi = i >> 2, M = i & 3;
        int a = 0, base = 0;
        while (base + (4 - a) <= pi) { base += 4 - a; a++; }
        int b = a + (pi - base);
        float v = g_cgw[a*256 + b*16 + M];
        if (a != b) v += g_cgw[b*256 + a*16 + M];
        g_sym2[i] = v;
    }
    if (t == 0) g_c000[0] = g_cgw[0];
}

// ---------------- embeddings, counting sort ----------------
__global__ void k_emb(const float* __restrict__ tab, const int* __restrict__ spec, int N) {
    int i = blockIdx.x * blockDim.x + threadIdx.x;
    if (i < N * 32) g_emb[i] = tab[spec[i >> 5] * 32 + (i & 31)];
}

__global__ void k_zeroCS(int N) {
    int i = blockIdx.x * blockDim.x + threadIdx.x;
    if (i < N) g_counts[i] = 0;
    if (i < N * 240) g_S[i] = 0.f;
}

__global__ void k_hist(const int* __restrict__ centers, int P) {
    int p = blockIdx.x * blockDim.x + threadIdx.x;
    if (p < P) atomicAdd(&g_counts[centers[p]], 1);
}

__global__ void k_scan(int N) {
    __shared__ int sh[1024];
    __shared__ int sCarry;
    int t = threadIdx.x;
    if (t == 0) sCarry = 0;
    __syncthreads();
    for (int base = 0; base < N; base += 1024) {
        int i = base + t;
        int v = (i < N) ? g_counts[i] : 0;
        sh[t] = v; __syncthreads();
        for (int off = 1; off < 1024; off <<= 1) {
            int tv = (t >= off) ? sh[t - off] : 0;
            __syncthreads();
            sh[t] += tv;
            __syncthreads();
        }
        int ex = sCarry + sh[t] - v;
        if (i < N) { g_starts[i] = ex; g_cursor[i] = ex; }
        __syncthreads();
        if (t == 0) sCarry += sh[1023];
        __syncthreads();
    }
}

__global__ void k_scatter(const int* __restrict__ centers, int P) {
    int p = blockIdx.x * blockDim.x + threadIdx.x;
    if (p < P) { int pos = atomicAdd(&g_cursor[centers[p]], 1); g_sorted[pos] = p; }
}

// ---------------- per-pair W precompute (sorted order) ----------------
__global__ void __launch_bounds__(256) k_W(const float* __restrict__ sh,
                                           const float* __restrict__ rb,
                                           const int* __restrict__ neighbors, int P) {
    int pos = blockIdx.x;
    if (pos >= P) return;
    int t = threadIdx.x;
    __shared__ float sE[16];
    int p = g_sorted[pos];
    if (t == 0) g_snbr[pos] = neighbors[p];
    if (t < 16) {
        int l   = (t==0)?0:(t<4)?1:(t<9)?2:3;
        int nrl = (l==0?8:l==1?6:l==2?4:2);
        int rbo = (l==0?0:l==1?8:l==2?14:18);
        float s = 0.f;
        for (int r = 0; r < nrl; r++) s += rb[p*20 + rbo + r];
        sE[t] = sh[p*16 + t] * 0.1f * s;
    }
    __syncthreads();
    float w = 0.f;
    #pragma unroll
    for (int a = 0; a < 16; a++) w += sE[a] * g_cgw[a*256 + t];
    g_W[(size_t)pos*256 + t] = w;
}

// ---------------- invariant MP ----------------
__global__ void k_invA(const float* __restrict__ sh, const float* __restrict__ rb,
                       const int* __restrict__ centers, const int* __restrict__ neighbors,
                       const int* __restrict__ spec, int P) {
    int idx = blockIdx.x * blockDim.x + threadIdx.x;
    int p = idx >> 6, j = idx & 63;
    if (p >= P || j >= 60) return;
    int l, m, nr;
    if (j < 8)       { l = 0; m = 0;        nr = j; }
    else if (j < 26) { l = 1; int r = j-8;  m = r/6; nr = r%6; }
    else if (j < 46) { l = 2; int r = j-26; m = r/4; nr = r%4; }
    else             { l = 3; int r = j-46; m = r/2; nr = r%2; }
    int shf = shoff(l) + m;
    int rbf = (l==0?0:l==1?8:l==2?14:18) + nr;
    float val = sh[p*16 + shf] * 0.1f * rb[p*20 + rbf];
    int s = spec[neighbors[p]];
    atomicAdd(&g_S[(centers[p]*4 + s)*60 + j], val);
}

__global__ void k_invB(const float* __restrict__ tab, int N) {
    int idx = blockIdx.x * blockDim.x + threadIdx.x;
    if (idx >= N * 1920) return;
    int n = idx / 1920, f = idx % 1920;
    int l, m, k;
    if (f < 256)       { l = 0; m = 0;         k = f; }
    else if (f < 832)  { l = 1; int r = f-256; m = r/192; k = r%192; }
    else if (f < 1472) { l = 2; int r = f-832; m = r/128; k = r%128; }
    else               { l = 3; int r = f-1472;m = r/64;  k = r%64; }
    int nr = k >> 5, c = k & 31;
    int nrl = (l==0?8:l==1?6:l==2?4:2);
    int jb  = (l==0?0:l==1?8:l==2?26:46);
    int j = jb + m*nrl + nr;
    const float* Sp = &g_S[n*240 + j];
    float s = 0.f;
    #pragma unroll
    for (int sp = 0; sp < 4; sp++) s += Sp[sp*60] * tab[sp*32 + c];
    g_feats[(size_t)n*1920 + f] = 0.1f * s;
}

// ---------------- tensor product, per k-class ----------------
__global__ void __launch_bounds__(256) k_tp0(int N) {   // k in [0,64): NF=16
    __shared__ float sC[136 * 16];
    int t = threadIdx.x;
    for (int i = t; i < 2176; i += 256) sC[i] = g_sym0[i];
    __syncthreads();
    int atom = blockIdx.x * 4 + (t >> 6);
    if (atom >= N) return;
    float* row = g_feats + (size_t)atom * 1920 + (t & 63);
    float A[16];
    A[0]=row[0];    A[1]=row[256];  A[2]=row[448];  A[3]=row[640];
    A[4]=row[832];  A[5]=row[960];  A[6]=row[1088]; A[7]=row[1216]; A[8]=row[1344];
    A[9]=row[1472]; A[10]=row[1536];A[11]=row[1600];A[12]=row[1664];
    A[13]=row[1728];A[14]=row[1792];A[15]=row[1856];
    ull acc[8];
    #pragma unroll
    for (int i = 0; i < 8; i++) acc[i] = 0ull;
    #pragma unroll
    for (int a = 0; a < 16; a++) {
        #pragma unroll
        for (int b = a; b < 16; b++) {
            const int pi = a*16 - a*(a-1)/2 + (b - a);
            float P = A[a] * A[b];
            ull Pd; PACK2(Pd, P);
            const ulonglong2* c2 = (const ulonglong2*)(sC + pi*16);
            ulonglong2 cv0 = c2[0];
            ulonglong2 cv1 = c2[1];
            FMA2(acc[0], Pd, cv0.x); FMA2(acc[1], Pd, cv0.y);
            FMA2(acc[2], Pd, cv1.x); FMA2(acc[3], Pd, cv1.y);
            ulonglong2 cv2 = c2[2];
            ulonglong2 cv3 = c2[3];
            FMA2(acc[4], Pd, cv2.x); FMA2(acc[5], Pd, cv2.y);
            FMA2(acc[6], Pd, cv3.x); FMA2(acc[7], Pd, cv3.y);
        }
    }
    float v[16];
    #pragma unroll
    for (int i = 0; i < 8; i++) UNPK2(v[2*i], v[2*i+1], acc[i]);
    row[0]   =A[0] +0.1f*v[0];  row[256] =A[1] +0.1f*v[1];  row[448] =A[2] +0.1f*v[2];
    row[640] =A[3] +0.1f*v[3];  row[832] =A[4] +0.1f*v[4];  row[960] =A[5] +0.1f*v[5];
    row[1088]=A[6] +0.1f*v[6];  row[1216]=A[7] +0.1f*v[7];  row[1344]=A[8] +0.1f*v[8];
    row[1472]=A[9] +0.1f*v[9];  row[1536]=A[10]+0.1f*v[10]; row[1600]=A[11]+0.1f*v[11];
    row[1664]=A[12]+0.1f*v[12]; row[1728]=A[13]+0.1f*v[13]; row[1792]=A[14]+0.1f*v[14];
    row[1856]=A[15]+0.1f*v[15];
}

__global__ void __launch_bounds__(256) k_tp1(int N) {   // k in [64,128): NF=9
    __shared__ float sC[45 * 16];
    int t = threadIdx.x;
    for (int i = t; i < 720; i += 256) sC[i] = g_sym1[i];
    __syncthreads();
    int atom = blockIdx.x * 4 + (t >> 6);
    if (atom >= N) return;
    float* row = g_feats + (size_t)atom * 1920 + 64 + (t & 63);
    float A[9];
    A[0]=row[0];   A[1]=row[256]; A[2]=row[448]; A[3]=row[640];
    A[4]=row[832]; A[5]=row[960]; A[6]=row[1088];A[7]=row[1216];A[8]=row[1344];
    ull acc[4];
    #pragma unroll
    for (int i = 0; i < 4; i++) acc[i] = 0ull;
    float acc8 = 0.f;
    #pragma unroll
    for (int a = 0; a < 9; a++) {
        #pragma unroll
        for (int b = a; b < 9; b++) {
            const int pi = a*9 - a*(a-1)/2 + (b - a);
            float P = A[a] * A[b];
            ull Pd; PACK2(Pd, P);
            const ulonglong2* c2 = (const ulonglong2*)(sC + pi*16);
            ulonglong2 cv0 = c2[0];
            ulonglong2 cv1 = c2[1];
            FMA2(acc[0], Pd, cv0.x); FMA2(acc[1], Pd, cv0.y);
            FMA2(acc[2], Pd, cv1.x); FMA2(acc[3], Pd, cv1.y);
            acc8 += P * sC[pi*16 + 8];
        }
    }
    float v[8];
    #pragma unroll
    for (int i = 0; i < 4; i++) UNPK2(v[2*i], v[2*i+1], acc[i]);
    row[0]   =A[0]+0.1f*v[0]; row[256] =A[1]+0.1f*v[1]; row[448] =A[2]+0.1f*v[2];
    row[640] =A[3]+0.1f*v[3]; row[832] =A[4]+0.1f*v[4]; row[960] =A[5]+0.1f*v[5];
    row[1088]=A[6]+0.1f*v[6]; row[1216]=A[7]+0.1f*v[7]; row[1344]=A[8]+0.1f*acc8;
}

__global__ void k_tp23(int N) {
    int t = threadIdx.x;
    int atom = blockIdx.x * 2 + (t >> 7);
    if (atom >= N) return;
    int tt = t & 127;
    if (tt < 64) {
        float* row = g_feats + (size_t)atom * 1920 + 128 + tt;
        float A[4];
        A[0]=row[0]; A[1]=row[256]; A[2]=row[448]; A[3]=row[640];
        float acc[4] = {0.f, 0.f, 0.f, 0.f};
        #pragma unroll
        for (int a = 0; a < 4; a++) {
            #pragma unroll
            for (int b = a; b < 4; b++) {
                const int pi = a*4 - a*(a-1)/2 + (b - a);
                float P = A[a] * A[b];
                #pragma unroll
                for (int M = 0; M < 4; M++) acc[M] += P * g_sym2[pi*4 + M];
            }
        }
        row[0]  =A[0]+0.1f*acc[0]; row[256]=A[1]+0.1f*acc[1];
        row[448]=A[2]+0.1f*acc[2]; row[640]=A[3]+0.1f*acc[3];
    } else {
        float* row = g_feats + (size_t)atom * 1920 + 192 + (tt & 63);
        float A = row[0];
        row[0] = A + 0.1f * A * A * g_c000[0];
    }
}

// ---------------- ef = feats * center_emb ----------------
__global__ void k_ef(int N) {
    size_t idx = blockIdx.x * (size_t)blockDim.x + threadIdx.x;
    if (idx >= (size_t)N * 1920) return;
    int n = (int)(idx / 1920); int f = (int)(idx % 1920);
    g_feats2[idx] = g_feats[idx] * g_emb[n*32 + (f & 31)];
}

// ---------------- equivariant MP v3: register EF, duplicated-W smem broadcast ----------------
template<int MF0,int NMF,int NB,int COLBASE>
__device__ __forceinline__ void roleFMA(ull* acc, const float* __restrict__ EFrow,
                                        const float* wbase, int lane) {
    ull ef[NB];
    #pragma unroll
    for (int b = 0; b < NB; b++)
        ef[b] = *(const ull*)(EFrow + OFFS[b] + COLBASE + 2*lane);
    #pragma unroll
    for (int mf = 0; mf < NMF; mf++) {
        #pragma unroll
        for (int b = 0; b < NB; b++) {
            ull wv = *(const ull*)(wbase + 2*(b*16 + MF0 + mf));
            FMA2(acc[mf], ef[b], wv);
        }
    }
}

template<int MF0,int NMF,int COLBASE>
__device__ __forceinline__ void roleStore(const ull* acc, float* orow, int lane) {
    #pragma unroll
    for (int mf = 0; mf < NMF; mf++) {
        float lo, hi; UNPK2(lo, hi, acc[mf]);
        *(float2*)(orow + OFFS[MF0+mf] + COLBASE + 2*lane) = make_float2(0.1f*lo, 0.1f*hi);
    }
}

__global__ void __launch_bounds__(256) k_eqmp2(int N) {
    __shared__ float sW[2][2][512];
    int t = threadIdx.x;
    int half = t >> 7, ht = t & 127;
    int wl = (t >> 5) & 3, lane = t & 31;
    int n = blockIdx.x * 2 + half;
    int start = 0, cnt = 0;
    if (n < N) { start = g_starts[n]; cnt = g_counts[n]; }
    ull A[9];
    #pragma unroll
    for (int i = 0; i < 9; i++) A[i] = 0ull;
    int barid = 1 + half;

    if (cnt > 0) {
        float2 v = *(const float2*)(g_W + (size_t)start*256 + 2*ht);
        *(float4*)&sW[half][0][4*ht] = make_float4(v.x, v.x, v.y, v.y);
    }
    asm volatile("bar.sync %0, 128;" :: "r"(barid) : "memory");

    for (int e = 0; e < cnt; e++) {
        if (e + 1 < cnt) {
            float2 v = *(const float2*)(g_W + (size_t)(start+e+1)*256 + 2*ht);
            *(float4*)&sW[half][(e+1)&1][4*ht] = make_float4(v.x, v.x, v.y, v.y);
        }
        const float* wbase = sW[half][e & 1];
        const float* EFrow = g_feats2 + (size_t)g_snbr[start + e] * 1920;
        if      (wl == 0) roleFMA<0,6,16,0>(A, EFrow, wbase, lane);
        else if (wl == 1) roleFMA<6,6,16,0>(A, EFrow, wbase, lane);
        else if (wl == 2) { roleFMA<12,4,16,0>(A,   EFrow, wbase, lane);
                            roleFMA<0,4,4,128>(A+4, EFrow, wbase, lane);
                            roleFMA<0,1,1,192>(A+8, EFrow, wbase, lane); }
        else              roleFMA<0,9,9,64>(A, EFrow, wbase, lane);
        asm volatile("bar.sync %0, 128;" :: "r"(barid) : "memory");
    }

    if (n < N) {
        float* orow = g_feats + (size_t)n * 1920;
        if      (wl == 0) roleStore<0,6,0>(A, orow, lane);
        else if (wl == 1) roleStore<6,6,0>(A, orow, lane);
        else if (wl == 2) { roleStore<12,4,0>(A,   orow, lane);
                            roleStore<0,4,128>(A+4, orow, lane);
                            roleStore<0,1,192>(A+8, orow, lane); }
        else              roleStore<0,9,64>(A, orow, lane);
    }
}

// ---------------- energy readout ----------------
__global__ void __launch_bounds__(256) k_energy(const float* __restrict__ wE,
                                                const float* __restrict__ bE,
                                                float* __restrict__ out, int N) {
    int n = blockIdx.x, t = threadIdx.x;
    float v = g_feats[(size_t)n*1920 + t] * g_emb[n*32 + (t & 31)] * wE[t];
    #pragma unroll
    for (int o = 16; o > 0; o >>= 1) v += __shfl_xor_sync(0xffffffffu, v, o);
    __shared__ float sred[8];
    if ((t & 31) == 0) sred[t >> 5] = v;
    __syncthreads();
    if (t == 0) {
        float s = 0.f;
        #pragma unroll
        for (int w = 0; w < 8; w++) s += sred[w];
        out[n] = s + bE[0];
    }
}

// ---------------- host: numpy RandomState(0).randn ----------------
static void gen_cg(float* out) {
    static uint32_t mt[624];
    int mti;
    mt[0] = 0;
    for (int i = 1; i < 624; i++)
        mt[i] = 1812433253u * (mt[i-1] ^ (mt[i-1] >> 30)) + (uint32_t)i;
    mti = 624;
    auto genrand = [&]() -> uint32_t {
        if (mti >= 624) {
            for (int i = 0; i < 624; i++) {
                uint32_t y = (mt[i] & 0x80000000u) | (mt[(i+1) % 624] & 0x7fffffffu);
                mt[i] = mt[(i+397) % 624] ^ (y >> 1) ^ ((y & 1u) ? 2567483615u : 0u);
            }
            mti = 0;
        }
        uint32_t y = mt[mti++];
        y ^= y >> 11; y ^= (y << 7) & 2636928640u; y ^= (y << 15) & 4022730752u; y ^= y >> 18;
        return y;
    };
    auto rdouble = [&]() -> double {
        uint32_t a = genrand() >> 5, b = genrand() >> 6;
        return (a * 67108864.0 + b) / 9007199254740992.0;
    };
    bool has_g = false; double gcache = 0.0;
    auto gauss = [&]() -> double {
        if (has_g) { has_g = false; return gcache; }
        double x1, x2, r2;
        do {
            x1 = 2.0 * rdouble() - 1.0;
            x2 = 2.0 * rdouble() - 1.0;
            r2 = x1*x1 + x2*x2;
        } while (r2 >= 1.0 || r2 == 0.0);
        double f = sqrt(-2.0 * log(r2) / r2);
        gcache = f * x1; has_g = true;
        return f * x2;
    };
    for (int i = 0; i < 3436; i++) out[i] = (float)(gauss() * 0.2);
}

static CGBuf h_cg;

extern "C" void kernel_launch(void* const* d_in, const int* in_sizes, int n_in,
                              void* d_out, int out_size) {
    const float* sh      = (const float*)d_in[0];
    const float* rb      = (const float*)d_in[1];
    const float* tab     = (const float*)d_in[2];
    const float* wE      = (const float*)d_in[3];
    const float* bE      = (const float*)d_in[4];
    const int*   spec    = (const int*)d_in[5];
    const int*   centers = (const int*)d_in[6];
    const int*   nbrs    = (const int*)d_in[7];
    int N = in_sizes[5];
    int P = in_sizes[6];
    float* out = (float*)d_out;

    gen_cg(h_cg.v);

    k_initcg<<<1, 256>>>(h_cg);
    k_emb<<<(N*32 + 255)/256, 256>>>(tab, spec, N);
    k_zeroCS<<<(N*240 + 255)/256, 256>>>(N);
    k_hist<<<(P + 255)/256, 256>>>(centers, P);
    k_scan<<<1, 1024>>>(N);
    k_scatter<<<(P + 255)/256, 256>>>(centers, P);
    k_W<<<P, 256>>>(sh, rb, nbrs, P);
    k_invA<<<(P*64 + 255)/256, 256>>>(sh, rb, centers, nbrs, spec, P);
    k_invB<<<(N*1920 + 255)/256, 256>>>(tab, N);
    k_tp0<<<(N + 3)/4, 256>>>(N);
    k_tp1<<<(N + 3)/4, 256>>>(N);
    k_tp23<<<(N + 1)/2, 256>>>(N);
    k_ef<<<(N*1920 + 255)/256, 256>>>(N);
    k_eqmp2<<<(N + 1)/2, 256>>>(N);
    k_tp0<<<(N + 3)/4, 256>>>(N);
    k_tp1<<<(N + 3)/4, 256>>>(N);
    k_tp23<<<(N + 1)/2, 256>>>(N);
    k_energy<<<N, 256>>>(wE, bE, out, N);
}